// round 3
// baseline (speedup 1.0000x reference)
#include <cuda_runtime.h>
#include <cstdint>

// Problem constants (fixed by reference): B=4, N=4096, PD=1024, D=16, S=64
#define BB   4
#define NN   4096
#define PD   1024
#define DD   16
#define SS   64
#define ALLC 1024          // D*S
#define MROWS (BB*NN)      // 16384

// Scratch (device globals; allocation-free rule). Padded P by 16 rows of slack
// (never actually read thanks to dmax guard, but belt-and-suspenders).
__device__ float g_P[(size_t)MROWS * 2 * ALLC];   // (b,n,2,16,64)  128 MB
__device__ float g_Q[(size_t)MROWS * ALLC];       // (b,n,16,64)     64 MB

// ---------------------------------------------------------------------------
// SGEMM with bias: C[M,Ncol] = A[M,K] @ B[K,Ncol] + bias[Ncol]
// 128x128 block tile, BK=8, 256 threads, 8x8 per-thread tile, smem double buffer.
// All dims divide tiles exactly for this problem (M=16384, N in {2048,1024}, K=1024).
// ---------------------------------------------------------------------------
__global__ __launch_bounds__(256, 2)
void sgemm_bias(const float* __restrict__ A, const float* __restrict__ B,
                const float* __restrict__ bias, float* __restrict__ C,
                int M, int Ncol, int K)
{
    __shared__ float As[2][8][128];
    __shared__ float Bs[2][8][128];

    const int tid = threadIdx.x;
    const int bx  = blockIdx.x;     // N tile
    const int by  = blockIdx.y;     // M tile

    const float* Ab = A + (size_t)by * 128 * K;
    const float* Bb = B + (size_t)bx * 128;

    // Global->smem load mapping (one float4 per thread per tile)
    const int arow = tid >> 1;             // 0..127
    const int acol = (tid & 1) << 2;       // 0 or 4
    const int brow = tid >> 5;             // 0..7
    const int bcol = (tid & 31) << 2;      // 0..124

    // Compute mapping: 16x16 thread grid, each owns rows {ty*4+i, 64+ty*4+i},
    // cols {tx*4+j, 64+tx*4+j}  (split halves -> conflict-free LDS.128)
    const int tx = tid & 15;
    const int ty = tid >> 4;

    float acc[8][8];
    #pragma unroll
    for (int i = 0; i < 8; i++)
        #pragma unroll
        for (int j = 0; j < 8; j++) acc[i][j] = 0.f;

    // Prologue: load tile 0
    float4 a4 = *(const float4*)(Ab + (size_t)arow * K + acol);
    float4 b4 = *(const float4*)(Bb + (size_t)brow * Ncol + bcol);
    As[0][acol + 0][arow] = a4.x; As[0][acol + 1][arow] = a4.y;
    As[0][acol + 2][arow] = a4.z; As[0][acol + 3][arow] = a4.w;
    *(float4*)&Bs[0][brow][bcol] = b4;
    __syncthreads();

    const int nk = K >> 3;
    int buf = 0;
    for (int kt = 0; kt < nk; ++kt) {
        // Prefetch next tile to registers while computing current
        if (kt + 1 < nk) {
            a4 = *(const float4*)(Ab + (size_t)arow * K + ((kt + 1) << 3) + acol);
            b4 = *(const float4*)(Bb + (size_t)(((kt + 1) << 3) + brow) * Ncol + bcol);
        }
        #pragma unroll
        for (int k = 0; k < 8; ++k) {
            float4 a0 = *(const float4*)&As[buf][k][ty * 4];
            float4 a1 = *(const float4*)&As[buf][k][64 + ty * 4];
            float4 b0 = *(const float4*)&Bs[buf][k][tx * 4];
            float4 b1 = *(const float4*)&Bs[buf][k][64 + tx * 4];
            float af[8] = {a0.x, a0.y, a0.z, a0.w, a1.x, a1.y, a1.z, a1.w};
            float bf[8] = {b0.x, b0.y, b0.z, b0.w, b1.x, b1.y, b1.z, b1.w};
            #pragma unroll
            for (int i = 0; i < 8; i++)
                #pragma unroll
                for (int j = 0; j < 8; j++)
                    acc[i][j] += af[i] * bf[j];
        }
        if (kt + 1 < nk) {
            buf ^= 1;
            As[buf][acol + 0][arow] = a4.x; As[buf][acol + 1][arow] = a4.y;
            As[buf][acol + 2][arow] = a4.z; As[buf][acol + 3][arow] = a4.w;
            *(float4*)&Bs[buf][brow][bcol] = b4;
            __syncthreads();
        }
    }

    // Epilogue: bias + store (float4)
    #pragma unroll
    for (int ih = 0; ih < 2; ih++) {
        #pragma unroll
        for (int ii = 0; ii < 4; ii++) {
            const int row = by * 128 + ih * 64 + ty * 4 + ii;
            #pragma unroll
            for (int jh = 0; jh < 2; jh++) {
                const int col = bx * 128 + jh * 64 + tx * 4;
                float4 bb = *(const float4*)(bias + col);
                float4 v;
                v.x = acc[ih * 4 + ii][jh * 4 + 0] + bb.x;
                v.y = acc[ih * 4 + ii][jh * 4 + 1] + bb.y;
                v.z = acc[ih * 4 + ii][jh * 4 + 2] + bb.z;
                v.w = acc[ih * 4 + ii][jh * 4 + 3] + bb.w;
                *(float4*)(C + (size_t)row * Ncol + col) = v;
            }
        }
    }
}

// ---------------------------------------------------------------------------
// Middle op, fully collapsed:
//   p[k]            = softmax_k( P[b,n,0,k,s] )                 (16-way)
//   Q[b,n,d*64+s]   = sum_{a=0}^{d-1} p[a] * P[b,n+a+1,1,d-1-a,s]
//   Q[.,0,.]        = 0
//   last group (t = n&15, g = n>>4 == 255): entries with t+d >= 16 -> 0
// Thread = one (b,n,s); block = 4 consecutive n x 64 s (all accesses coalesced
// across s; heavy L1/L2 reuse of P1 rows across overlapping n).
// ---------------------------------------------------------------------------
__global__ __launch_bounds__(256)
void middle_kernel(const float* __restrict__ P, float* __restrict__ Q)
{
    const int s   = threadIdx.x & 63;
    const int sub = threadIdx.x >> 6;              // 0..3
    const int bn  = blockIdx.x * 4 + sub;          // 0 .. B*N-1
    const int n   = bn & (NN - 1);
    const int t   = n & 15;
    const int g   = n >> 4;
    const bool last = (g == (NN / 16) - 1);

    const float* base = P + (size_t)bn * (2 * ALLC) + s;   // P[b,n,0,0,s]

    // 16-way softmax of the P0 row (pads underflow to exp=0 in the reference,
    // so only the 16 finite entries matter)
    float v[16];
    float m = -1e30f;
    #pragma unroll
    for (int k = 0; k < 16; k++) { v[k] = base[k * 64]; m = fmaxf(m, v[k]); }
    float sum = 0.f;
    #pragma unroll
    for (int k = 0; k < 16; k++) { v[k] = __expf(v[k] - m); sum += v[k]; }
    const float inv = 1.0f / sum;

    float out[16];
    #pragma unroll
    for (int d = 0; d < 16; d++) out[d] = 0.f;

    // r_a[c] = P[b, n+1+a, 1, c, s]; row stride between n is 2048 floats.
    const float* r0 = base + ALLC + 2 * ALLC;      // row n+1, channel 1

    if (!last) {
        #pragma unroll
        for (int a = 0; a < 15; a++) {
            const float pa = v[a] * inv;
            const float* ra = r0 + (size_t)a * (2 * ALLC);
            #pragma unroll
            for (int c = 0; c < 15 - a; c++)
                out[a + 1 + c] += pa * ra[c * 64];
        }
    } else {
        const int dmax = 15 - t;   // entries with t+d>=16 are masked to zero;
                                   // guard also keeps every row read in-range.
        #pragma unroll
        for (int a = 0; a < 15; a++) {
            const float pa = v[a] * inv;
            const float* ra = r0 + (size_t)a * (2 * ALLC);
            #pragma unroll
            for (int c = 0; c < 15 - a; c++)
                if (a + 1 + c <= dmax)
                    out[a + 1 + c] += pa * ra[c * 64];
        }
    }

    float* q = Q + (size_t)bn * ALLC + s;
    #pragma unroll
    for (int d = 0; d < 16; d++) q[d * 64] = out[d];
}

// ---------------------------------------------------------------------------
extern "C" void kernel_launch(void* const* d_in, const int* in_sizes, int n_in,
                              void* d_out, int out_size)
{
    const float* x   = (const float*)d_in[0];   // (B,N,PD)
    const float* W_r = (const float*)d_in[1];   // (PD, 2*ALL)
    const float* b_r = (const float*)d_in[2];   // (2*ALL,)
    const float* W_w = (const float*)d_in[3];   // (ALL, PD)
    const float* b_w = (const float*)d_in[4];   // (PD,)
    float* out = (float*)d_out;

    float *P, *Q;
    cudaGetSymbolAddress((void**)&P, g_P);
    cudaGetSymbolAddress((void**)&Q, g_Q);

    // GEMM1: P = x @ W_r + b_r   (16384 x 2048 x 1024)
    sgemm_bias<<<dim3(2 * ALLC / 128, MROWS / 128), 256>>>(
        x, W_r, b_r, P, MROWS, 2 * ALLC, PD);

    // Middle: softmax + stencil -> Q
    middle_kernel<<<MROWS / 4, 256>>>(P, Q);

    // GEMM2: out = Q @ W_w + b_w  (16384 x 1024 x 1024)
    sgemm_bias<<<dim3(PD / 128, MROWS / 128), 256>>>(
        Q, W_w, b_w, out, MROWS, PD, ALLC);
}

// round 11
// speedup vs baseline: 2.3143x; 2.3143x over previous
#include <cuda_runtime.h>
#include <cstdint>

// Problem constants: B=4, N=4096, PD=1024, D=16, S=64
#define NN   4096
#define PD   1024
#define ALLC 1024
#define MROWS 16384

// Scratch (device globals; allocation-free rule)
__device__ float g_P[(size_t)MROWS * 2 * ALLC];     // 128 MB
__device__ float g_Q[(size_t)MROWS * ALLC];         //  64 MB
__device__ float g_Wrt[(size_t)2 * ALLC * PD];      //   8 MB  W_r^T (N-major, K contig)
__device__ float g_Wwt[(size_t)PD * ALLC];          //   4 MB  W_w^T

// ---------------------------------------------------------------------------
// Helpers
// ---------------------------------------------------------------------------
__device__ __forceinline__ uint32_t smem_u32(const void* p) {
    uint32_t a;
    asm("{ .reg .u64 t; cvta.to.shared.u64 t, %1; cvt.u32.u64 %0, t; }"
        : "=r"(a) : "l"(p));
    return a;
}
__device__ __forceinline__ void cp_async16(uint32_t s, const void* g) {
    asm volatile("cp.async.cg.shared.global [%0], [%1], 16;" :: "r"(s), "l"(g));
}
#define CP_COMMIT() asm volatile("cp.async.commit_group;" ::: "memory")
#define CP_WAIT(n)  asm volatile("cp.async.wait_group %0;" :: "n"(n) : "memory")

// Round-to-nearest f32 -> tf32 (bits in a b32 reg). RN is load-bearing:
// truncation would bias each GEMM by ~5e-4 and blow the 1e-3 budget.
__device__ __forceinline__ uint32_t f2tf32(float x) {
    uint32_t r;
    asm("cvt.rna.tf32.f32 %0, %1;" : "=r"(r) : "f"(x));
    return r;
}

__device__ __forceinline__ void mma8(float* c, const uint32_t* a, const uint32_t* b) {
    asm volatile(
        "mma.sync.aligned.m16n8k8.row.col.f32.tf32.tf32.f32 "
        "{%0,%1,%2,%3}, {%4,%5,%6,%7}, {%8,%9}, {%0,%1,%2,%3};"
        : "+f"(c[0]), "+f"(c[1]), "+f"(c[2]), "+f"(c[3])
        : "r"(a[0]), "r"(a[1]), "r"(a[2]), "r"(a[3]), "r"(b[0]), "r"(b[1]));
}

// ---------------------------------------------------------------------------
// tf32 mma.sync GEMM: C[M,Ncol] = A[M,K] @ Bt[Ncol,K]^T + bias
// CTA tile 128x128, BK=16, 256 threads (8 warps of 64x32), 4-stage cp.async.
// SMEM rows padded to stride 20 floats -> fragment LDS is conflict-free
// (bank = (20*group + quad) % 32 covers all 32 banks exactly once).
// ---------------------------------------------------------------------------
#define STAGES 4
#define SA_STR 20                          // floats per smem row (16 data + 4 pad)
#define HALF_FLOATS (128 * SA_STR)         // 2560 (A or B half of a stage)
#define STAGE_FLOATS (2 * HALF_FLOATS)     // 5120
#define GEMM_SMEM (STAGES * STAGE_FLOATS * 4)   // 81920 B

__global__ __launch_bounds__(256, 2)
void gemm_mma(const float* __restrict__ A, const float* __restrict__ Bt,
              const float* __restrict__ bias, float* __restrict__ C,
              int Ncol, int K)
{
    extern __shared__ float sm[];
    const int tid  = threadIdx.x;
    const int w    = tid >> 5, l = tid & 31;
    const int wm   = w >> 2,  wn = w & 3;       // warp grid 2(m) x 4(n)
    const int grp  = l >> 2,  quad = l & 3;
    const int m0   = blockIdx.y * 128;
    const int n0   = blockIdx.x * 128;

    const float* Ag = A  + (size_t)m0 * K;
    const float* Bg = Bt + (size_t)n0 * K;
    const uint32_t sb = smem_u32(sm);

    float acc[4][4][4];
    #pragma unroll
    for (int i = 0; i < 4; i++)
        #pragma unroll
        for (int j = 0; j < 4; j++)
            #pragma unroll
            for (int k = 0; k < 4; k++) acc[i][j][k] = 0.f;

    auto load_chunk = [&](int kc, int st) {
        const uint32_t sA = sb + (uint32_t)st * STAGE_FLOATS * 4;
        const uint32_t sB = sA + HALF_FLOATS * 4;
        #pragma unroll
        for (int i = 0; i < 2; i++) {           // A: 128 rows x 4 f4
            int idx = i * 256 + tid;
            int row = idx >> 2, c4 = idx & 3;
            cp_async16(sA + (row * SA_STR + c4 * 4) * 4,
                       Ag + (size_t)row * K + kc * 16 + c4 * 4);
        }
        #pragma unroll
        for (int i = 0; i < 2; i++) {           // B: 128 rows x 4 f4
            int idx = i * 256 + tid;
            int row = idx >> 2, c4 = idx & 3;
            cp_async16(sB + (row * SA_STR + c4 * 4) * 4,
                       Bg + (size_t)row * K + kc * 16 + c4 * 4);
        }
    };

    const int KCH = K >> 4;                    // 16-float K chunks (=64 here)
    #pragma unroll
    for (int j = 0; j < STAGES - 1; j++) { load_chunk(j, j); CP_COMMIT(); }

    for (int kc = 0; kc < KCH; kc++) {
        CP_WAIT(STAGES - 2);                    // chunk kc resident
        __syncthreads();                        // all warps done with stage (kc-1)%4
        const int jl = kc + STAGES - 1;
        if (jl < KCH) load_chunk(jl, jl & 3);   // overwrites stage (kc-1)%4: safe
        CP_COMMIT();                            // one group per iter, always

        const float* As = sm + (size_t)(kc & 3) * STAGE_FLOATS;
        const float* Bs = As + HALF_FLOATS;

        #pragma unroll
        for (int s2 = 0; s2 < 2; s2++) {        // two k=8 steps
            uint32_t af[4][4], bf[4][2];
            #pragma unroll
            for (int i = 0; i < 4; i++) {
                const float* ap = As + (wm * 64 + i * 16 + grp) * SA_STR + s2 * 8 + quad;
                af[i][0] = f2tf32(ap[0]);
                af[i][1] = f2tf32(ap[8 * SA_STR]);
                af[i][2] = f2tf32(ap[4]);
                af[i][3] = f2tf32(ap[8 * SA_STR + 4]);
            }
            #pragma unroll
            for (int j = 0; j < 4; j++) {       // B pre-rounded to tf32
                const float* bp = Bs + (wn * 32 + j * 8 + grp) * SA_STR + s2 * 8 + quad;
                bf[j][0] = __float_as_uint(bp[0]);
                bf[j][1] = __float_as_uint(bp[4]);
            }
            #pragma unroll
            for (int i = 0; i < 4; i++)
                #pragma unroll
                for (int j = 0; j < 4; j++)
                    mma8(acc[i][j], af[i], bf[j]);
        }
    }

    // Epilogue: bias + float2 stores
    #pragma unroll
    for (int i = 0; i < 4; i++) {
        const int r = m0 + wm * 64 + i * 16 + grp;
        #pragma unroll
        for (int j = 0; j < 4; j++) {
            const int c = n0 + wn * 32 + j * 8 + quad * 2;
            float2 bv = *(const float2*)(bias + c);
            float2 v0 = { acc[i][j][0] + bv.x, acc[i][j][1] + bv.y };
            float2 v1 = { acc[i][j][2] + bv.x, acc[i][j][3] + bv.y };
            *(float2*)(C + (size_t)r * Ncol + c)       = v0;
            *(float2*)(C + (size_t)(r + 8) * Ncol + c) = v1;
        }
    }
}

// ---------------------------------------------------------------------------
// Transpose + tf32 rounding: out[C][R] = tf32(in[R][C])
// ---------------------------------------------------------------------------
__global__ __launch_bounds__(256)
void transpose_k(const float* __restrict__ in, float* __restrict__ out,
                 int R, int C)
{
    __shared__ float t[32][33];
    const int bx = blockIdx.x * 32, by = blockIdx.y * 32;
    #pragma unroll
    for (int i = 0; i < 4; i++)
        t[threadIdx.y + i * 8][threadIdx.x] =
            in[(size_t)(by + threadIdx.y + i * 8) * C + bx + threadIdx.x];
    __syncthreads();
    #pragma unroll
    for (int i = 0; i < 4; i++)
        out[(size_t)(bx + threadIdx.y + i * 8) * R + by + threadIdx.x] =
            __uint_as_float(f2tf32(t[threadIdx.x][threadIdx.y + i * 8]));
}

// ---------------------------------------------------------------------------
// Middle op (proven correct in R3) + tf32 rounding of Q on store:
//   p = softmax_16(P0 row);  Q[b,n,d*64+s] = sum_a p[a]*P1[b,n+a+1,d-1-a,s]
// ---------------------------------------------------------------------------
__global__ __launch_bounds__(256)
void middle_kernel(const float* __restrict__ P, float* __restrict__ Q)
{
    const int s   = threadIdx.x & 63;
    const int sub = threadIdx.x >> 6;
    const int bn  = blockIdx.x * 4 + sub;
    const int n   = bn & (NN - 1);
    const int t   = n & 15;
    const int g   = n >> 4;
    const bool last = (g == (NN / 16) - 1);

    const float* base = P + (size_t)bn * (2 * ALLC) + s;

    float v[16];
    float m = -1e30f;
    #pragma unroll
    for (int k = 0; k < 16; k++) { v[k] = base[k * 64]; m = fmaxf(m, v[k]); }
    float sum = 0.f;
    #pragma unroll
    for (int k = 0; k < 16; k++) { v[k] = __expf(v[k] - m); sum += v[k]; }
    const float inv = 1.0f / sum;

    float out[16];
    #pragma unroll
    for (int d = 0; d < 16; d++) out[d] = 0.f;

    const float* r0 = base + ALLC + 2 * ALLC;

    if (!last) {
        #pragma unroll
        for (int a = 0; a < 15; a++) {
            const float pa = v[a] * inv;
            const float* ra = r0 + (size_t)a * (2 * ALLC);
            #pragma unroll
            for (int c = 0; c < 15 - a; c++)
                out[a + 1 + c] += pa * ra[c * 64];
        }
    } else {
        const int dmax = 15 - t;
        #pragma unroll
        for (int a = 0; a < 15; a++) {
            const float pa = v[a] * inv;
            const float* ra = r0 + (size_t)a * (2 * ALLC);
            #pragma unroll
            for (int c = 0; c < 15 - a; c++)
                if (a + 1 + c <= dmax)
                    out[a + 1 + c] += pa * ra[c * 64];
        }
    }

    float* q = Q + (size_t)bn * ALLC + s;
    #pragma unroll
    for (int d = 0; d < 16; d++)
        q[d * 64] = __uint_as_float(f2tf32(out[d]));   // pre-round for GEMM2 B... (A side)
}

// ---------------------------------------------------------------------------
extern "C" void kernel_launch(void* const* d_in, const int* in_sizes, int n_in,
                              void* d_out, int out_size)
{
    const float* x   = (const float*)d_in[0];   // (B,N,PD)
    const float* W_r = (const float*)d_in[1];   // (PD, 2*ALL)
    const float* b_r = (const float*)d_in[2];
    const float* W_w = (const float*)d_in[3];   // (ALL, PD)
    const float* b_w = (const float*)d_in[4];
    float* out = (float*)d_out;

    float *P, *Q, *Wrt, *Wwt;
    cudaGetSymbolAddress((void**)&P,   g_P);
    cudaGetSymbolAddress((void**)&Q,   g_Q);
    cudaGetSymbolAddress((void**)&Wrt, g_Wrt);
    cudaGetSymbolAddress((void**)&Wwt, g_Wwt);

    cudaFuncSetAttribute(gemm_mma,
                         cudaFuncAttributeMaxDynamicSharedMemorySize, GEMM_SMEM);

    // One-time weight transposes (+ tf32 rounding)
    transpose_k<<<dim3(2 * ALLC / 32, PD / 32), dim3(32, 8)>>>(W_r, Wrt, PD, 2 * ALLC);
    transpose_k<<<dim3(PD / 32, ALLC / 32),     dim3(32, 8)>>>(W_w, Wwt, ALLC, PD);

    // GEMM1: P = x @ W_r + b_r   (16384 x 2048 x 1024)
    gemm_mma<<<dim3(2 * ALLC / 128, MROWS / 128), 256, GEMM_SMEM>>>(
        x, Wrt, b_r, P, 2 * ALLC, PD);

    // Middle: softmax + stencil -> Q (tf32-rounded)
    middle_kernel<<<MROWS / 4, 256>>>(P, Q);

    // GEMM2: out = Q @ W_w + b_w  (16384 x 1024 x 1024)
    gemm_mma<<<dim3(PD / 128, MROWS / 128), 256, GEMM_SMEM>>>(
        Q, Wwt, b_w, out, PD, ALLC);
}

// round 12
// speedup vs baseline: 3.4995x; 1.5121x over previous
#include <cuda_runtime.h>
#include <cuda_fp16.h>
#include <cstdint>

// Problem constants: B=4, N=4096, PD=1024, D=16, S=64
#define NN   4096
#define PD   1024
#define ALLC 1024
#define MROWS 16384

// Scratch (device globals; allocation-free rule)
__device__ float  g_P[(size_t)MROWS * 2 * ALLC];    // 128 MB (GEMM1 out, f32)
__device__ __half g_Q[(size_t)MROWS * ALLC];        //  32 MB (middle out, fp16)
__device__ __half g_xh[(size_t)MROWS * PD];         //  33 MB x in fp16
__device__ __half g_Wrt[(size_t)2 * ALLC * PD];     //   4 MB W_r^T fp16 (K contig)
__device__ __half g_Wwt[(size_t)PD * ALLC];         //   2 MB W_w^T fp16

// ---------------------------------------------------------------------------
// Helpers
// ---------------------------------------------------------------------------
__device__ __forceinline__ uint32_t smem_u32(const void* p) {
    uint32_t a;
    asm("{ .reg .u64 t; cvta.to.shared.u64 t, %1; cvt.u32.u64 %0, t; }"
        : "=r"(a) : "l"(p));
    return a;
}
__device__ __forceinline__ void cp_async16(uint32_t s, const void* g) {
    asm volatile("cp.async.cg.shared.global [%0], [%1], 16;" :: "r"(s), "l"(g));
}
#define CP_COMMIT() asm volatile("cp.async.commit_group;" ::: "memory")
#define CP_WAIT(n)  asm volatile("cp.async.wait_group %0;" :: "n"(n) : "memory")

#define LDSM4(R0, R1, R2, R3, A) \
    asm volatile("ldmatrix.sync.aligned.m8n8.x4.shared.b16 {%0,%1,%2,%3}, [%4];" \
        : "=r"(R0), "=r"(R1), "=r"(R2), "=r"(R3) : "r"(A))

__device__ __forceinline__ void mma16(float* c, const uint32_t* a, const uint32_t* b) {
    asm volatile(
        "mma.sync.aligned.m16n8k16.row.col.f32.f16.f16.f32 "
        "{%0,%1,%2,%3}, {%4,%5,%6,%7}, {%8,%9}, {%0,%1,%2,%3};"
        : "+f"(c[0]), "+f"(c[1]), "+f"(c[2]), "+f"(c[3])
        : "r"(a[0]), "r"(a[1]), "r"(a[2]), "r"(a[3]), "r"(b[0]), "r"(b[1]));
}

// ---------------------------------------------------------------------------
// fp16 mma.sync GEMM: C[M,Ncol](f32) = A[M,K](f16) @ Bt[Ncol,K](f16)^T + bias
// CTA 128x128, BK=32 halves, 256 threads (8 warps of 64x32), 4-stage cp.async.
// SMEM row stride 40 halves (80 B): cp.async stores AND ldmatrix phases both
// map 8 rows/chunks onto all 8 16B bank-groups ((5r+c) mod 8 bijective).
// ---------------------------------------------------------------------------
#define STAGES 4
#define ROW_B 80                               // bytes per smem row (64 data + 16 pad)
#define HALF_STAGE (128 * ROW_B)               // 10240 B (A or B half)
#define STAGE_BYTES (2 * HALF_STAGE)           // 20480 B
#define GEMM_SMEM (STAGES * STAGE_BYTES)       // 81920 B

__global__ __launch_bounds__(256, 2)
void gemm_f16(const __half* __restrict__ A, const __half* __restrict__ Bt,
              const float* __restrict__ bias, float* __restrict__ C,
              int Ncol, int K)
{
    extern __shared__ char sm[];
    const uint32_t sb = smem_u32(sm);
    const int tid = threadIdx.x;
    const int w   = tid >> 5, l = tid & 31;
    const int wm  = w >> 2,  wn = w & 3;       // warp grid 2(m) x 4(n)
    const int m0  = blockIdx.y * 128;
    const int n0  = blockIdx.x * 128;

    const __half* Ag = A  + (size_t)m0 * K;
    const __half* Bg = Bt + (size_t)n0 * K;

    float acc[4][4][4];
    #pragma unroll
    for (int i = 0; i < 4; i++)
        #pragma unroll
        for (int j = 0; j < 4; j++)
            #pragma unroll
            for (int k = 0; k < 4; k++) acc[i][j][k] = 0.f;

    // cp.async mapping: idx in [0,512): c16 = idx>>7 (0..3), row = idx&127
    // -> consecutive tids hit distinct bank-groups (5r mod 8 bijective).
    auto load_chunk = [&](int kc, int st) {
        const uint32_t sA = sb + (uint32_t)st * STAGE_BYTES;
        const uint32_t sB = sA + HALF_STAGE;
        #pragma unroll
        for (int i = 0; i < 2; i++) {
            int idx = i * 256 + tid;
            int c = idx >> 7, row = idx & 127;
            cp_async16(sA + row * ROW_B + c * 16,
                       Ag + (size_t)row * K + kc * 32 + c * 8);
        }
        #pragma unroll
        for (int i = 0; i < 2; i++) {
            int idx = i * 256 + tid;
            int c = idx >> 7, row = idx & 127;
            cp_async16(sB + row * ROW_B + c * 16,
                       Bg + (size_t)row * K + kc * 32 + c * 8);
        }
    };

    const int KCH = K >> 5;                    // 32-half K chunks
    #pragma unroll
    for (int j = 0; j < STAGES - 1; j++) { load_chunk(j, j); CP_COMMIT(); }

    // Per-thread ldmatrix address components (byte offsets within a stage)
    // A x4 matrices: m0=(rows0-7,k0) m1=(rows8-15,k0) m2=(rows0-7,k8) m3=(rows8-15,k8)
    const uint32_t aoff = (uint32_t)(wm * 64 + (l & 15)) * ROW_B + (l >> 4) * 16;
    // B x4 matrices: m0=(n0-7,k0) m1=(n0-7,k8) m2=(n8-15,k0) m3=(n8-15,k8)
    const uint32_t boff = (uint32_t)(wn * 32 + ((l >> 4) << 3) + (l & 7)) * ROW_B
                        + ((l >> 3) & 1) * 16;

    for (int kc = 0; kc < KCH; kc++) {
        CP_WAIT(STAGES - 2);                   // chunk kc resident
        __syncthreads();                       // all warps done with stage (kc-1)&3
        const int jl = kc + STAGES - 1;
        if (jl < KCH) load_chunk(jl, jl & 3);
        CP_COMMIT();                           // one group per iter, always

        const uint32_t base  = sb + (uint32_t)(kc & 3) * STAGE_BYTES;
        const uint32_t baseB = base + HALF_STAGE;

        #pragma unroll
        for (int s2 = 0; s2 < 2; s2++) {       // two k16 steps per chunk
            uint32_t a[4][4], b[4][2];
            #pragma unroll
            for (int i = 0; i < 4; i++)
                LDSM4(a[i][0], a[i][1], a[i][2], a[i][3],
                      base + aoff + (uint32_t)i * 16 * ROW_B + s2 * 32);
            #pragma unroll
            for (int jp = 0; jp < 2; jp++) {
                uint32_t r0, r1, r2, r3;
                LDSM4(r0, r1, r2, r3,
                      baseB + boff + (uint32_t)jp * 16 * ROW_B + s2 * 32);
                b[2 * jp][0] = r0; b[2 * jp][1] = r1;
                b[2 * jp + 1][0] = r2; b[2 * jp + 1][1] = r3;
            }
            #pragma unroll
            for (int i = 0; i < 4; i++)
                #pragma unroll
                for (int j = 0; j < 4; j++)
                    mma16(acc[i][j], a[i], b[j]);
        }
    }

    // Epilogue: bias + float2 stores (fragment rows t/4, cols 2*(t%4))
    const int grp = l >> 2, quad = l & 3;
    #pragma unroll
    for (int i = 0; i < 4; i++) {
        const int r = m0 + wm * 64 + i * 16 + grp;
        #pragma unroll
        for (int j = 0; j < 4; j++) {
            const int c = n0 + wn * 32 + j * 8 + quad * 2;
            float2 bv = *(const float2*)(bias + c);
            float2 v0 = { acc[i][j][0] + bv.x, acc[i][j][1] + bv.y };
            float2 v1 = { acc[i][j][2] + bv.x, acc[i][j][3] + bv.y };
            *(float2*)(C + (size_t)r * Ncol + c)       = v0;
            *(float2*)(C + (size_t)(r + 8) * Ncol + c) = v1;
        }
    }
}

// ---------------------------------------------------------------------------
// f32 -> f16 convert (for x), vectorized float4 -> 4 halves
// ---------------------------------------------------------------------------
__global__ __launch_bounds__(256)
void convert_h(const float* __restrict__ in, __half* __restrict__ out, int n4)
{
    int i = blockIdx.x * 256 + threadIdx.x;
    if (i < n4) {
        float4 v = ((const float4*)in)[i];
        __half2 h0 = __floats2half2_rn(v.x, v.y);
        __half2 h1 = __floats2half2_rn(v.z, v.w);
        uint2 o = { *(uint32_t*)&h0, *(uint32_t*)&h1 };
        ((uint2*)out)[i] = o;
    }
}

// ---------------------------------------------------------------------------
// Transpose + f16 rounding: out[C][R] = f16(in[R][C])
// ---------------------------------------------------------------------------
__global__ __launch_bounds__(256)
void transpose_k(const float* __restrict__ in, __half* __restrict__ out,
                 int R, int C)
{
    __shared__ float t[32][33];
    const int bx = blockIdx.x * 32, by = blockIdx.y * 32;
    #pragma unroll
    for (int i = 0; i < 4; i++)
        t[threadIdx.y + i * 8][threadIdx.x] =
            in[(size_t)(by + threadIdx.y + i * 8) * C + bx + threadIdx.x];
    __syncthreads();
    #pragma unroll
    for (int i = 0; i < 4; i++)
        out[(size_t)(bx + threadIdx.y + i * 8) * R + by + threadIdx.x] =
            __float2half_rn(t[threadIdx.x][threadIdx.y + i * 8]);
}

// ---------------------------------------------------------------------------
// Middle op (proven since R3): p = softmax_16(P0 row);
//   Q[b,n,d*64+s] = sum_a p[a] * P1[b,n+a+1,d-1-a,s]; fp16 output for GEMM2.
// ---------------------------------------------------------------------------
__global__ __launch_bounds__(256)
void middle_kernel(const float* __restrict__ P, __half* __restrict__ Q)
{
    const int s   = threadIdx.x & 63;
    const int sub = threadIdx.x >> 6;
    const int bn  = blockIdx.x * 4 + sub;
    const int n   = bn & (NN - 1);
    const int t   = n & 15;
    const int g   = n >> 4;
    const bool last = (g == (NN / 16) - 1);

    const float* base = P + (size_t)bn * (2 * ALLC) + s;

    float v[16];
    float m = -1e30f;
    #pragma unroll
    for (int k = 0; k < 16; k++) { v[k] = base[k * 64]; m = fmaxf(m, v[k]); }
    float sum = 0.f;
    #pragma unroll
    for (int k = 0; k < 16; k++) { v[k] = __expf(v[k] - m); sum += v[k]; }
    const float inv = 1.0f / sum;

    float out[16];
    #pragma unroll
    for (int d = 0; d < 16; d++) out[d] = 0.f;

    const float* r0 = base + ALLC + 2 * ALLC;

    if (!last) {
        #pragma unroll
        for (int a = 0; a < 15; a++) {
            const float pa = v[a] * inv;
            const float* ra = r0 + (size_t)a * (2 * ALLC);
            #pragma unroll
            for (int c = 0; c < 15 - a; c++)
                out[a + 1 + c] += pa * ra[c * 64];
        }
    } else {
        const int dmax = 15 - t;
        #pragma unroll
        for (int a = 0; a < 15; a++) {
            const float pa = v[a] * inv;
            const float* ra = r0 + (size_t)a * (2 * ALLC);
            #pragma unroll
            for (int c = 0; c < 15 - a; c++)
                if (a + 1 + c <= dmax)
                    out[a + 1 + c] += pa * ra[c * 64];
        }
    }

    __half* q = Q + (size_t)bn * ALLC + s;
    #pragma unroll
    for (int d = 0; d < 16; d++) q[d * 64] = __float2half_rn(out[d]);
}

// ---------------------------------------------------------------------------
extern "C" void kernel_launch(void* const* d_in, const int* in_sizes, int n_in,
                              void* d_out, int out_size)
{
    const float* x   = (const float*)d_in[0];   // (B,N,PD)
    const float* W_r = (const float*)d_in[1];   // (PD, 2*ALL)
    const float* b_r = (const float*)d_in[2];
    const float* W_w = (const float*)d_in[3];   // (ALL, PD)
    const float* b_w = (const float*)d_in[4];
    float* out = (float*)d_out;

    float  *P;
    __half *Q, *xh, *Wrt, *Wwt;
    cudaGetSymbolAddress((void**)&P,   g_P);
    cudaGetSymbolAddress((void**)&Q,   g_Q);
    cudaGetSymbolAddress((void**)&xh,  g_xh);
    cudaGetSymbolAddress((void**)&Wrt, g_Wrt);
    cudaGetSymbolAddress((void**)&Wwt, g_Wwt);

    cudaFuncSetAttribute(gemm_f16,
                         cudaFuncAttributeMaxDynamicSharedMemorySize, GEMM_SMEM);

    // x -> fp16
    const int n4 = MROWS * PD / 4;
    convert_h<<<(n4 + 255) / 256, 256>>>(x, xh, n4);
    // Weight transposes (+ fp16 rounding)
    transpose_k<<<dim3(2 * ALLC / 32, PD / 32), dim3(32, 8)>>>(W_r, Wrt, PD, 2 * ALLC);
    transpose_k<<<dim3(PD / 32, ALLC / 32),     dim3(32, 8)>>>(W_w, Wwt, ALLC, PD);

    // GEMM1: P = x @ W_r + b_r   (16384 x 2048 x 1024)
    gemm_f16<<<dim3(2 * ALLC / 128, MROWS / 128), 256, GEMM_SMEM>>>(
        xh, Wrt, b_r, P, 2 * ALLC, PD);

    // Middle: softmax + stencil -> Q (fp16)
    middle_kernel<<<MROWS / 4, 256>>>(P, Q);

    // GEMM2: out = Q @ W_w + b_w  (16384 x 1024 x 1024)
    gemm_f16<<<dim3(PD / 128, MROWS / 128), 256, GEMM_SMEM>>>(
        Q, Wwt, b_w, out, PD, ALLC);
}